// round 1
// baseline (speedup 1.0000x reference)
#include <cuda_runtime.h>
#include <math.h>

#define BB 4
#define CC 512
#define CQ 64
#define NN 4096

// Scratch (device globals; no runtime allocation allowed)
__device__ float g_Q[(size_t)BB * NN * CQ];   // [B][N][Cq]  (transposed Q)
__device__ float g_K[(size_t)BB * CQ * NN];   // [B][Cq][N]
__device__ float g_V[(size_t)BB * CC * NN];   // [B][C][N]
__device__ float g_P[(size_t)BB * NN * NN];   // [B][N][N]  energy -> attn

// ---------------------------------------------------------------------------
// Generic projection GEMM:  Y[M][NN] = W[M][CC] * X[CC][NN]   (per batch b)
// block tile 64x64, K-step 16, 256 threads, 4x4 per thread.
// TRANS=true stores Y transposed as [NN][M] (used for Q).
// ---------------------------------------------------------------------------
template <int M, bool TRANS>
__global__ void proj_kernel(const float* __restrict__ W,
                            const float* __restrict__ X,
                            float* __restrict__ Y) {
    __shared__ float As[64 * 17];   // W tile [m][k], padded
    __shared__ float Bs[16 * 64];   // X tile [k][n]

    const int b  = blockIdx.z;
    const float* Xb = X + (size_t)b * CC * NN;
    const int n0 = blockIdx.x * 64;
    const int m0 = blockIdx.y * 64;
    const int tid = threadIdx.x;
    const int tx = tid & 15;        // n direction
    const int ty = tid >> 4;        // m direction

    float acc[4][4] = {};

    for (int k0 = 0; k0 < CC; k0 += 16) {
        {   // load W tile (64x16), 4 contiguous floats/thread
            int lin = tid * 4;
            int m = lin >> 4, k = lin & 15;
            float4 v = *(const float4*)(W + (size_t)(m0 + m) * CC + k0 + k);
            As[m * 17 + k + 0] = v.x; As[m * 17 + k + 1] = v.y;
            As[m * 17 + k + 2] = v.z; As[m * 17 + k + 3] = v.w;
        }
        {   // load X tile (16x64)
            int lin = tid * 4;
            int k = lin >> 6, n = lin & 63;
            *(float4*)(Bs + k * 64 + n) =
                *(const float4*)(Xb + (size_t)(k0 + k) * NN + n0 + n);
        }
        __syncthreads();
        #pragma unroll
        for (int kk = 0; kk < 16; kk++) {
            float a[4], bv[4];
            #pragma unroll
            for (int i = 0; i < 4; i++) a[i] = As[(ty * 4 + i) * 17 + kk];
            #pragma unroll
            for (int j = 0; j < 4; j++) bv[j] = Bs[kk * 64 + tx * 4 + j];
            #pragma unroll
            for (int i = 0; i < 4; i++)
                #pragma unroll
                for (int j = 0; j < 4; j++)
                    acc[i][j] += a[i] * bv[j];
        }
        __syncthreads();
    }

    if (TRANS) {
        float* Yb = Y + (size_t)b * NN * M;
        #pragma unroll
        for (int i = 0; i < 4; i++)
            #pragma unroll
            for (int j = 0; j < 4; j++)
                Yb[(size_t)(n0 + tx * 4 + j) * M + (m0 + ty * 4 + i)] = acc[i][j];
    } else {
        float* Yb = Y + (size_t)b * M * NN;
        #pragma unroll
        for (int i = 0; i < 4; i++)
            #pragma unroll
            for (int j = 0; j < 4; j++)
                Yb[(size_t)(m0 + ty * 4 + i) * NN + (n0 + tx * 4 + j)] = acc[i][j];
    }
}

// ---------------------------------------------------------------------------
// Energy GEMM:  P[i][j] = sum_o Q[i][o] * K[o][j]   (K dim = 64)
// ---------------------------------------------------------------------------
__global__ void energy_kernel(const float* __restrict__ Q,
                              const float* __restrict__ K,
                              float* __restrict__ P) {
    __shared__ float As[64 * 17];   // Q tile [i][o]
    __shared__ float Bs[16 * 64];   // K tile [o][j]

    const int b  = blockIdx.z;
    const float* Qb = Q + (size_t)b * NN * CQ;
    const float* Kb = K + (size_t)b * CQ * NN;
    float* Pb = P + (size_t)b * NN * NN;

    const int j0 = blockIdx.x * 64;
    const int i0 = blockIdx.y * 64;
    const int tid = threadIdx.x;
    const int tx = tid & 15;        // j
    const int ty = tid >> 4;        // i

    float acc[4][4] = {};

    for (int k0 = 0; k0 < CQ; k0 += 16) {
        {
            int lin = tid * 4;
            int m = lin >> 4, k = lin & 15;
            float4 v = *(const float4*)(Qb + (size_t)(i0 + m) * CQ + k0 + k);
            As[m * 17 + k + 0] = v.x; As[m * 17 + k + 1] = v.y;
            As[m * 17 + k + 2] = v.z; As[m * 17 + k + 3] = v.w;
        }
        {
            int lin = tid * 4;
            int k = lin >> 6, n = lin & 63;
            *(float4*)(Bs + k * 64 + n) =
                *(const float4*)(Kb + (size_t)(k0 + k) * NN + j0 + n);
        }
        __syncthreads();
        #pragma unroll
        for (int kk = 0; kk < 16; kk++) {
            float a[4], bv[4];
            #pragma unroll
            for (int i = 0; i < 4; i++) a[i] = As[(ty * 4 + i) * 17 + kk];
            #pragma unroll
            for (int j = 0; j < 4; j++) bv[j] = Bs[kk * 64 + tx * 4 + j];
            #pragma unroll
            for (int i = 0; i < 4; i++)
                #pragma unroll
                for (int j = 0; j < 4; j++)
                    acc[i][j] += a[i] * bv[j];
        }
        __syncthreads();
    }

    #pragma unroll
    for (int i = 0; i < 4; i++)
        #pragma unroll
        for (int j = 0; j < 4; j++)
            Pb[(size_t)(i0 + ty * 4 + i) * NN + (j0 + tx * 4 + j)] = acc[i][j];
}

// ---------------------------------------------------------------------------
// Row softmax over keys (last dim). One block per (b, row). 256 threads,
// 16 elements/thread held in registers: single read + single write of P.
// ---------------------------------------------------------------------------
__global__ void softmax_kernel(float* __restrict__ P) {
    const size_t roff = ((size_t)blockIdx.y * NN + blockIdx.x) * (size_t)NN;
    float4* p4 = (float4*)(P + roff);
    const int tid = threadIdx.x;

    __shared__ float sh_max[8];
    __shared__ float sh_sum[8];
    __shared__ float sh_bcast;

    float4 v[4];
    float m = -1e30f;
    #pragma unroll
    for (int q = 0; q < 4; q++) {
        v[q] = p4[tid + q * 256];
        m = fmaxf(m, fmaxf(fmaxf(v[q].x, v[q].y), fmaxf(v[q].z, v[q].w)));
    }
    // block max
    #pragma unroll
    for (int o = 16; o > 0; o >>= 1) m = fmaxf(m, __shfl_xor_sync(0xffffffffu, m, o));
    if ((tid & 31) == 0) sh_max[tid >> 5] = m;
    __syncthreads();
    if (tid == 0) {
        float t = sh_max[0];
        #pragma unroll
        for (int w = 1; w < 8; w++) t = fmaxf(t, sh_max[w]);
        sh_bcast = t;
    }
    __syncthreads();
    m = sh_bcast;

    float s = 0.f;
    #pragma unroll
    for (int q = 0; q < 4; q++) {
        v[q].x = expf(v[q].x - m); v[q].y = expf(v[q].y - m);
        v[q].z = expf(v[q].z - m); v[q].w = expf(v[q].w - m);
        s += v[q].x + v[q].y + v[q].z + v[q].w;
    }
    #pragma unroll
    for (int o = 16; o > 0; o >>= 1) s += __shfl_xor_sync(0xffffffffu, s, o);
    if ((tid & 31) == 0) sh_sum[tid >> 5] = s;
    __syncthreads();
    if (tid == 0) {
        float t = 0.f;
        #pragma unroll
        for (int w = 0; w < 8; w++) t += sh_sum[w];
        sh_bcast = 1.0f / t;
    }
    __syncthreads();
    const float inv = sh_bcast;

    #pragma unroll
    for (int q = 0; q < 4; q++) {
        v[q].x *= inv; v[q].y *= inv; v[q].z *= inv; v[q].w *= inv;
        p4[tid + q * 256] = v[q];
    }
}

// ---------------------------------------------------------------------------
// Output GEMM:  out[c][i] = gamma * sum_j V[c][j] * P[i][j]  + x[c][i]
// Both operands are j-major (K-major): load both tiles as [row][16j] padded.
// ---------------------------------------------------------------------------
__global__ void out_kernel(const float* __restrict__ V,
                           const float* __restrict__ P,
                           const float* __restrict__ x,
                           const float* __restrict__ gamma,
                           float* __restrict__ out) {
    __shared__ float As[64 * 17];   // V tile [c][j]
    __shared__ float Bs[64 * 17];   // P tile [i][j]

    const int b  = blockIdx.z;
    const float* Vb = V + (size_t)b * CC * NN;
    const float* Pb = P + (size_t)b * NN * NN;

    const int i0 = blockIdx.x * 64;   // query/pixel index
    const int c0 = blockIdx.y * 64;   // channel index
    const int tid = threadIdx.x;
    const int tx = tid & 15;          // i direction
    const int ty = tid >> 4;          // c direction

    float acc[4][4] = {};

    for (int j0 = 0; j0 < NN; j0 += 16) {
        {
            int lin = tid * 4;
            int m = lin >> 4, k = lin & 15;
            float4 v = *(const float4*)(Vb + (size_t)(c0 + m) * NN + j0 + k);
            As[m * 17 + k + 0] = v.x; As[m * 17 + k + 1] = v.y;
            As[m * 17 + k + 2] = v.z; As[m * 17 + k + 3] = v.w;
        }
        {
            int lin = tid * 4;
            int m = lin >> 4, k = lin & 15;
            float4 v = *(const float4*)(Pb + (size_t)(i0 + m) * NN + j0 + k);
            Bs[m * 17 + k + 0] = v.x; Bs[m * 17 + k + 1] = v.y;
            Bs[m * 17 + k + 2] = v.z; Bs[m * 17 + k + 3] = v.w;
        }
        __syncthreads();
        #pragma unroll
        for (int jj = 0; jj < 16; jj++) {
            float a[4], bv[4];
            #pragma unroll
            for (int i = 0; i < 4; i++) a[i] = As[(ty * 4 + i) * 17 + jj];
            #pragma unroll
            for (int j = 0; j < 4; j++) bv[j] = Bs[(tx * 4 + j) * 17 + jj];
            #pragma unroll
            for (int i = 0; i < 4; i++)
                #pragma unroll
                for (int j = 0; j < 4; j++)
                    acc[i][j] += a[i] * bv[j];
        }
        __syncthreads();
    }

    const float g = gamma[0];
    #pragma unroll
    for (int i = 0; i < 4; i++) {
        #pragma unroll
        for (int j = 0; j < 4; j++) {
            int c = c0 + ty * 4 + i;
            int n = i0 + tx * 4 + j;
            size_t idx = ((size_t)b * CC + c) * NN + n;
            out[idx] = g * acc[i][j] + x[idx];
        }
    }
}

// ---------------------------------------------------------------------------
extern "C" void kernel_launch(void* const* d_in, const int* in_sizes, int n_in,
                              void* d_out, int out_size) {
    const float* x     = (const float*)d_in[0];
    const float* Wq    = (const float*)d_in[1];
    const float* Wk    = (const float*)d_in[2];
    const float* Wv    = (const float*)d_in[3];
    const float* gamma = (const float*)d_in[4];
    float* out = (float*)d_out;

    float *Q, *K, *V, *P;
    cudaGetSymbolAddress((void**)&Q, g_Q);
    cudaGetSymbolAddress((void**)&K, g_K);
    cudaGetSymbolAddress((void**)&V, g_V);
    cudaGetSymbolAddress((void**)&P, g_P);

    dim3 blk(256);

    // Projections
    proj_kernel<CQ, true ><<<dim3(NN / 64, CQ / 64, BB), blk>>>(Wq, x, Q);
    proj_kernel<CQ, false><<<dim3(NN / 64, CQ / 64, BB), blk>>>(Wk, x, K);
    proj_kernel<CC, false><<<dim3(NN / 64, CC / 64, BB), blk>>>(Wv, x, V);

    // Energy
    energy_kernel<<<dim3(NN / 64, NN / 64, BB), blk>>>(Q, K, P);

    // Softmax over keys
    softmax_kernel<<<dim3(NN, BB), blk>>>(P);

    // Output GEMM + epilogue
    out_kernel<<<dim3(NN / 64, CC / 64, BB), blk>>>(V, P, x, gamma, out);
}

// round 3
// speedup vs baseline: 1.7019x; 1.7019x over previous
#include <cuda_runtime.h>
#include <math.h>
#include <cstdint>
#include <mma.h>

using namespace nvcuda;

#define BB 4
#define CC 512
#define CQ 64
#define NN 4096

// Scratch (device globals; no runtime allocation allowed)
__device__ float g_Q[(size_t)BB * NN * CQ];   // [B][N][Cq]  (transposed Q)
__device__ float g_K[(size_t)BB * CQ * NN];   // [B][Cq][N]
__device__ float g_V[(size_t)BB * CC * NN];   // [B][C][N]
__device__ float g_P[(size_t)BB * NN * NN];   // [B][N][N]  energy -> attn

// ===========================================================================
// WMMA tf32 NN GEMM:  C[m][n] = sum_k A[m][k] * B[k][n]
// Block tile 128x128, K-chunk 32, 256 threads (8 warps, 4x2 warp grid),
// each warp computes 32x64 via 2x4 wmma 16x16x8 fragments.
// Register-prefetch pipelining of global loads.
// ===========================================================================
#define ASTRIDE 40    // A smem row stride (floats)
#define BSTRIDE 136   // B smem row stride (floats), [32][128]
#define SMEM_NN_FLOATS (128 * ASTRIDE + 32 * BSTRIDE)
#define SMEM_NN_BYTES  (SMEM_NN_FLOATS * 4)

__global__ void __launch_bounds__(256, 1)
wmma_nn_kernel(const float* __restrict__ A, const float* __restrict__ B,
               float* __restrict__ C, int Kdim, int lda, int ldb, int ldc,
               size_t strideA, size_t strideB, size_t strideC) {
    extern __shared__ float sm[];
    float* As = sm;                  // [128][ASTRIDE]
    float* Bs = sm + 128 * ASTRIDE;  // [32][BSTRIDE]

    const int bz = blockIdx.z;
    const int m0 = blockIdx.y * 128;
    const int n0 = blockIdx.x * 128;
    const float* Ab = A + bz * strideA + (size_t)m0 * lda;
    const float* Bb = B + bz * strideB + n0;
    float* Cb = C + bz * strideC;

    const int tid = threadIdx.x;
    const int wid = tid >> 5;
    const int wm = wid >> 1;   // 0..3 -> m offset wm*32
    const int wn = wid & 1;    // 0..1 -> n offset wn*64

    wmma::fragment<wmma::accumulator, 16, 16, 8, float> acc[2][4];
    #pragma unroll
    for (int f = 0; f < 2; f++)
        #pragma unroll
        for (int g = 0; g < 4; g++)
            wmma::fill_fragment(acc[f][g], 0.0f);

    float4 ra[4], rb[4];
    // A tile: 128 rows x 8 float4 segs = 1024 tasks -> 4/thread
    // B tile: 32 rows x 32 float4 segs = 1024 tasks -> 4/thread
    #pragma unroll
    for (int k = 0; k < 4; k++) {
        int t = tid + k * 256;
        ra[k] = *(const float4*)(Ab + (size_t)(t >> 3) * lda + (t & 7) * 4);
        rb[k] = *(const float4*)(Bb + (size_t)(t >> 5) * ldb + (t & 31) * 4);
    }

    for (int k0 = 0; k0 < Kdim; k0 += 32) {
        #pragma unroll
        for (int k = 0; k < 4; k++) {
            int t = tid + k * 256;
            *(float4*)(As + (t >> 3) * ASTRIDE + (t & 7) * 4) = ra[k];
            *(float4*)(Bs + (t >> 5) * BSTRIDE + (t & 31) * 4) = rb[k];
        }
        __syncthreads();

        if (k0 + 32 < Kdim) {
            #pragma unroll
            for (int k = 0; k < 4; k++) {
                int t = tid + k * 256;
                ra[k] = *(const float4*)(Ab + (size_t)(t >> 3) * lda + k0 + 32 + (t & 7) * 4);
                rb[k] = *(const float4*)(Bb + (size_t)(k0 + 32 + (t >> 5)) * ldb + (t & 31) * 4);
            }
        }

        #pragma unroll
        for (int kk = 0; kk < 4; kk++) {
            wmma::fragment<wmma::matrix_a, 16, 16, 8, wmma::precision::tf32, wmma::row_major> af[2];
            wmma::fragment<wmma::matrix_b, 16, 16, 8, wmma::precision::tf32, wmma::row_major> bf[4];
            #pragma unroll
            for (int f = 0; f < 2; f++) {
                wmma::load_matrix_sync(af[f], As + (wm * 32 + f * 16) * ASTRIDE + kk * 8, ASTRIDE);
                #pragma unroll
                for (int e = 0; e < af[f].num_elements; e++)
                    af[f].x[e] = wmma::__float_to_tf32(af[f].x[e]);
            }
            #pragma unroll
            for (int g = 0; g < 4; g++) {
                wmma::load_matrix_sync(bf[g], Bs + kk * 8 * BSTRIDE + wn * 64 + g * 16, BSTRIDE);
                #pragma unroll
                for (int e = 0; e < bf[g].num_elements; e++)
                    bf[g].x[e] = wmma::__float_to_tf32(bf[g].x[e]);
            }
            #pragma unroll
            for (int f = 0; f < 2; f++)
                #pragma unroll
                for (int g = 0; g < 4; g++)
                    wmma::mma_sync(acc[f][g], af[f], bf[g], acc[f][g]);
        }
        __syncthreads();
    }

    #pragma unroll
    for (int f = 0; f < 2; f++)
        #pragma unroll
        for (int g = 0; g < 4; g++)
            wmma::store_matrix_sync(
                Cb + (size_t)(m0 + wm * 32 + f * 16) * ldc + n0 + wn * 64 + g * 16,
                acc[f][g], ldc, wmma::mem_row_major);
}

// ===========================================================================
// WMMA tf32 NT GEMM with epilogue:
//   out[b][c][i] = gamma * sum_j V[b][c][j] * P[b][i][j] + x[b][c][i]
// A = V [c][j] row-major (k=j), B = P [i][j] -> matrix_b col_major.
// ===========================================================================
#define EPSTRIDE 132
#define SMEM_OUT_FLOATS (128 * EPSTRIDE)   // 16896 (> 2*128*ASTRIDE = 10240)
#define SMEM_OUT_BYTES  (SMEM_OUT_FLOATS * 4)

__global__ void __launch_bounds__(256, 1)
wmma_out_kernel(const float* __restrict__ V, const float* __restrict__ P,
                const float* __restrict__ x, const float* __restrict__ gamma,
                float* __restrict__ out) {
    extern __shared__ float sm[];
    float* As = sm;                  // [128][ASTRIDE]  V tile
    float* Bs = sm + 128 * ASTRIDE;  // [128][ASTRIDE]  P tile
    float* Ep = sm;                  // epilogue alias [128][EPSTRIDE]

    const int b  = blockIdx.z;
    const int c0 = blockIdx.y * 128;
    const int i0 = blockIdx.x * 128;
    const float* Vb = V + ((size_t)b * CC + c0) * NN;
    const float* Pb = P + ((size_t)b * NN + i0) * NN;

    const int tid = threadIdx.x;
    const int wid = tid >> 5;
    const int wm = wid >> 1;
    const int wn = wid & 1;

    wmma::fragment<wmma::accumulator, 16, 16, 8, float> acc[2][4];
    #pragma unroll
    for (int f = 0; f < 2; f++)
        #pragma unroll
        for (int g = 0; g < 4; g++)
            wmma::fill_fragment(acc[f][g], 0.0f);

    float4 ra[4], rb[4];
    // Both tiles: 128 rows x 8 segs = 1024 tasks -> 4/thread
    #pragma unroll
    for (int k = 0; k < 4; k++) {
        int t = tid + k * 256;
        ra[k] = *(const float4*)(Vb + (size_t)(t >> 3) * NN + (t & 7) * 4);
        rb[k] = *(const float4*)(Pb + (size_t)(t >> 3) * NN + (t & 7) * 4);
    }

    for (int j0 = 0; j0 < NN; j0 += 32) {
        #pragma unroll
        for (int k = 0; k < 4; k++) {
            int t = tid + k * 256;
            *(float4*)(As + (t >> 3) * ASTRIDE + (t & 7) * 4) = ra[k];
            *(float4*)(Bs + (t >> 3) * ASTRIDE + (t & 7) * 4) = rb[k];
        }
        __syncthreads();

        if (j0 + 32 < NN) {
            #pragma unroll
            for (int k = 0; k < 4; k++) {
                int t = tid + k * 256;
                ra[k] = *(const float4*)(Vb + (size_t)(t >> 3) * NN + j0 + 32 + (t & 7) * 4);
                rb[k] = *(const float4*)(Pb + (size_t)(t >> 3) * NN + j0 + 32 + (t & 7) * 4);
            }
        }

        #pragma unroll
        for (int kk = 0; kk < 4; kk++) {
            wmma::fragment<wmma::matrix_a, 16, 16, 8, wmma::precision::tf32, wmma::row_major> af[2];
            wmma::fragment<wmma::matrix_b, 16, 16, 8, wmma::precision::tf32, wmma::col_major> bf[4];
            #pragma unroll
            for (int f = 0; f < 2; f++) {
                wmma::load_matrix_sync(af[f], As + (wm * 32 + f * 16) * ASTRIDE + kk * 8, ASTRIDE);
                #pragma unroll
                for (int e = 0; e < af[f].num_elements; e++)
                    af[f].x[e] = wmma::__float_to_tf32(af[f].x[e]);
            }
            #pragma unroll
            for (int g = 0; g < 4; g++) {
                // col_major: element(k,n) = ptr[n*ldm + k]
                wmma::load_matrix_sync(bf[g], Bs + (wn * 64 + g * 16) * ASTRIDE + kk * 8, ASTRIDE);
                #pragma unroll
                for (int e = 0; e < bf[g].num_elements; e++)
                    bf[g].x[e] = wmma::__float_to_tf32(bf[g].x[e]);
            }
            #pragma unroll
            for (int f = 0; f < 2; f++)
                #pragma unroll
                for (int g = 0; g < 4; g++)
                    wmma::mma_sync(acc[f][g], af[f], bf[g], acc[f][g]);
        }
        __syncthreads();
    }

    // Stage accumulators to smem, then fused epilogue out = g*acc + x
    #pragma unroll
    for (int f = 0; f < 2; f++)
        #pragma unroll
        for (int g = 0; g < 4; g++)
            wmma::store_matrix_sync(Ep + (wm * 32 + f * 16) * EPSTRIDE + wn * 64 + g * 16,
                                    acc[f][g], EPSTRIDE, wmma::mem_row_major);
    __syncthreads();

    const float gm = gamma[0];
    #pragma unroll
    for (int t = tid; t < 128 * 32; t += 256) {
        int r = t >> 5, s = t & 31;
        float4 a = *(const float4*)(Ep + r * EPSTRIDE + s * 4);
        size_t gi = ((size_t)b * CC + c0 + r) * NN + i0 + s * 4;
        float4 xv = *(const float4*)(x + gi);
        float4 o;
        o.x = gm * a.x + xv.x;
        o.y = gm * a.y + xv.y;
        o.z = gm * a.z + xv.z;
        o.w = gm * a.w + xv.w;
        *(float4*)(out + gi) = o;
    }
}

// ---------------------------------------------------------------------------
// Projection GEMM (FFMA, used for Q and K only — small):
//   Y[M][NN] = W[M][CC] * X[CC][NN], TRANS stores Y as [NN][M].
// ---------------------------------------------------------------------------
template <int M, bool TRANS>
__global__ void proj_kernel(const float* __restrict__ W,
                            const float* __restrict__ X,
                            float* __restrict__ Y) {
    __shared__ float As[64 * 17];
    __shared__ float Bs[16 * 64];

    const int b  = blockIdx.z;
    const float* Xb = X + (size_t)b * CC * NN;
    const int n0 = blockIdx.x * 64;
    const int m0 = blockIdx.y * 64;
    const int tid = threadIdx.x;
    const int tx = tid & 15;
    const int ty = tid >> 4;

    float acc[4][4] = {};

    for (int k0 = 0; k0 < CC; k0 += 16) {
        {
            int lin = tid * 4;
            int m = lin >> 4, k = lin & 15;
            float4 v = *(const float4*)(W + (size_t)(m0 + m) * CC + k0 + k);
            As[m * 17 + k + 0] = v.x; As[m * 17 + k + 1] = v.y;
            As[m * 17 + k + 2] = v.z; As[m * 17 + k + 3] = v.w;
        }
        {
            int lin = tid * 4;
            int k = lin >> 6, n = lin & 63;
            *(float4*)(Bs + k * 64 + n) =
                *(const float4*)(Xb + (size_t)(k0 + k) * NN + n0 + n);
        }
        __syncthreads();
        #pragma unroll
        for (int kk = 0; kk < 16; kk++) {
            float a[4], bv[4];
            #pragma unroll
            for (int i = 0; i < 4; i++) a[i] = As[(ty * 4 + i) * 17 + kk];
            #pragma unroll
            for (int j = 0; j < 4; j++) bv[j] = Bs[kk * 64 + tx * 4 + j];
            #pragma unroll
            for (int i = 0; i < 4; i++)
                #pragma unroll
                for (int j = 0; j < 4; j++)
                    acc[i][j] += a[i] * bv[j];
        }
        __syncthreads();
    }

    if (TRANS) {
        float* Yb = Y + (size_t)b * NN * M;
        #pragma unroll
        for (int i = 0; i < 4; i++)
            #pragma unroll
            for (int j = 0; j < 4; j++)
                Yb[(size_t)(n0 + tx * 4 + j) * M + (m0 + ty * 4 + i)] = acc[i][j];
    } else {
        float* Yb = Y + (size_t)b * M * NN;
        #pragma unroll
        for (int i = 0; i < 4; i++)
            #pragma unroll
            for (int j = 0; j < 4; j++)
                Yb[(size_t)(m0 + ty * 4 + i) * NN + (n0 + tx * 4 + j)] = acc[i][j];
    }
}

// ---------------------------------------------------------------------------
// Row softmax over keys (last dim). One block per (b, row), 256 threads.
// ---------------------------------------------------------------------------
__global__ void softmax_kernel(float* __restrict__ P) {
    const size_t roff = ((size_t)blockIdx.y * NN + blockIdx.x) * (size_t)NN;
    float4* p4 = (float4*)(P + roff);
    const int tid = threadIdx.x;

    __shared__ float sh_max[8];
    __shared__ float sh_sum[8];
    __shared__ float sh_bcast;

    float4 v[4];
    float m = -1e30f;
    #pragma unroll
    for (int q = 0; q < 4; q++) {
        v[q] = p4[tid + q * 256];
        m = fmaxf(m, fmaxf(fmaxf(v[q].x, v[q].y), fmaxf(v[q].z, v[q].w)));
    }
    #pragma unroll
    for (int o = 16; o > 0; o >>= 1) m = fmaxf(m, __shfl_xor_sync(0xffffffffu, m, o));
    if ((tid & 31) == 0) sh_max[tid >> 5] = m;
    __syncthreads();
    if (tid == 0) {
        float t = sh_max[0];
        #pragma unroll
        for (int w = 1; w < 8; w++) t = fmaxf(t, sh_max[w]);
        sh_bcast = t;
    }
    __syncthreads();
    m = sh_bcast;

    float s = 0.f;
    #pragma unroll
    for (int q = 0; q < 4; q++) {
        v[q].x = expf(v[q].x - m); v[q].y = expf(v[q].y - m);
        v[q].z = expf(v[q].z - m); v[q].w = expf(v[q].w - m);
        s += v[q].x + v[q].y + v[q].z + v[q].w;
    }
    #pragma unroll
    for (int o = 16; o > 0; o >>= 1) s += __shfl_xor_sync(0xffffffffu, s, o);
    if ((tid & 31) == 0) sh_sum[tid >> 5] = s;
    __syncthreads();
    if (tid == 0) {
        float t = 0.f;
        #pragma unroll
        for (int w = 0; w < 8; w++) t += sh_sum[w];
        sh_bcast = 1.0f / t;
    }
    __syncthreads();
    const float inv = sh_bcast;

    #pragma unroll
    for (int q = 0; q < 4; q++) {
        v[q].x *= inv; v[q].y *= inv; v[q].z *= inv; v[q].w *= inv;
        p4[tid + q * 256] = v[q];
    }
}

// ---------------------------------------------------------------------------
extern "C" void kernel_launch(void* const* d_in, const int* in_sizes, int n_in,
                              void* d_out, int out_size) {
    const float* x     = (const float*)d_in[0];
    const float* Wq    = (const float*)d_in[1];
    const float* Wk    = (const float*)d_in[2];
    const float* Wv    = (const float*)d_in[3];
    const float* gamma = (const float*)d_in[4];
    float* out = (float*)d_out;

    float *Q, *K, *V, *P;
    cudaGetSymbolAddress((void**)&Q, g_Q);
    cudaGetSymbolAddress((void**)&K, g_K);
    cudaGetSymbolAddress((void**)&V, g_V);
    cudaGetSymbolAddress((void**)&P, g_P);

    cudaFuncSetAttribute(wmma_nn_kernel,
                         cudaFuncAttributeMaxDynamicSharedMemorySize, SMEM_NN_BYTES);
    cudaFuncSetAttribute(wmma_out_kernel,
                         cudaFuncAttributeMaxDynamicSharedMemorySize, SMEM_OUT_BYTES);

    dim3 blk(256);

    // Q, K projections (FFMA; small)
    proj_kernel<CQ, true ><<<dim3(NN / 64, CQ / 64, BB), blk>>>(Wq, x, Q);
    proj_kernel<CQ, false><<<dim3(NN / 64, CQ / 64, BB), blk>>>(Wk, x, K);

    // V projection (WMMA tf32): A=Wv [512][512], B=x [512][4096], C=V
    wmma_nn_kernel<<<dim3(NN / 128, CC / 128, BB), blk, SMEM_NN_BYTES>>>(
        Wv, x, V, CC, CC, NN, NN,
        0, (size_t)CC * NN, (size_t)CC * NN);

    // Energy (WMMA tf32): A=Q [4096][64], B=K [64][4096], C=P
    wmma_nn_kernel<<<dim3(NN / 128, NN / 128, BB), blk, SMEM_NN_BYTES>>>(
        Q, K, P, CQ, CQ, NN, NN,
        (size_t)NN * CQ, (size_t)CQ * NN, (size_t)NN * NN);

    // Softmax over keys
    softmax_kernel<<<dim3(NN, BB), blk>>>(P);

    // Output GEMM + fused epilogue (WMMA tf32, B transposed)
    wmma_out_kernel<<<dim3(NN / 128, CC / 128, BB), blk, SMEM_OUT_BYTES>>>(
        V, P, x, gamma, out);
}

// round 4
// speedup vs baseline: 1.9693x; 1.1572x over previous
#include <cuda_runtime.h>
#include <math.h>
#include <cstdint>
#include <mma.h>

using namespace nvcuda;

#define BB 4
#define CC 512
#define CQ 64
#define NN 4096

// Scratch (device globals; no runtime allocation allowed)
__device__ float g_Q[(size_t)BB * NN * CQ];   // [B][N][Cq]  (transposed Q)
__device__ float g_K[(size_t)BB * CQ * NN];   // [B][Cq][N]
__device__ float g_V[(size_t)BB * CC * NN];   // [B][C][N]
__device__ float g_P[(size_t)BB * NN * NN];   // [B][N][N]  energy -> attn

__device__ __forceinline__ uint32_t smem_u32(const void* p) {
    uint32_t a;
    asm("{ .reg .u64 t; cvta.to.shared.u64 t, %1; cvt.u32.u64 %0, t; }"
        : "=r"(a) : "l"(p));
    return a;
}
#define CP_ASYNC16(dst_u32, src_ptr) \
    asm volatile("cp.async.cg.shared.global [%0], [%1], 16;" \
                 :: "r"(dst_u32), "l"(src_ptr) : "memory")
#define CP_COMMIT() asm volatile("cp.async.commit_group;" ::: "memory")
#define CP_WAIT(n)  asm volatile("cp.async.wait_group %0;" :: "n"(n) : "memory")

// ===========================================================================
// WMMA tf32 NN GEMM:  C[m][n] = sum_k A[m][k] * B[k][n]
// Block tile 128x128, K-chunk 32, 256 threads (8 warps, 4x2 warp grid),
// 2-stage cp.async pipeline, no explicit tf32 cvt (HW truncates).
// ===========================================================================
#define ASTRIDE 40    // A smem row stride (floats)
#define BSTRIDE 136   // B smem row stride (floats)
#define NN_STAGE_FLOATS (128 * ASTRIDE + 32 * BSTRIDE)   // 9472
#define SMEM_NN_BYTES   (2 * NN_STAGE_FLOATS * 4)        // 75776

__global__ void __launch_bounds__(256, 2)
wmma_nn_kernel(const float* __restrict__ A, const float* __restrict__ B,
               float* __restrict__ C, int Kdim, int lda, int ldb, int ldc,
               size_t strideA, size_t strideB, size_t strideC) {
    extern __shared__ float sm[];

    const int bz = blockIdx.z;
    const int m0 = blockIdx.y * 128;
    const int n0 = blockIdx.x * 128;
    const float* Ab = A + bz * strideA + (size_t)m0 * lda;
    const float* Bb = B + bz * strideB + n0;
    float* Cb = C + bz * strideC;

    const int tid = threadIdx.x;
    const int wid = tid >> 5;
    const int wm = wid >> 1;   // m offset wm*32
    const int wn = wid & 1;    // n offset wn*64

    // per-thread cp.async tasks (4 A + 4 B segments of 16B per chunk)
    const int ar = tid >> 1;              // A rows: tid,tid+256.. -> rows (t>>3)? recompute below
    (void)ar;

    wmma::fragment<wmma::accumulator, 16, 16, 8, float> acc[2][4];
    #pragma unroll
    for (int f = 0; f < 2; f++)
        #pragma unroll
        for (int g = 0; g < 4; g++)
            wmma::fill_fragment(acc[f][g], 0.0f);

    const uint32_t smb = smem_u32(sm);

    // issue one chunk's loads into stage s
    auto issue = [&](int k0, int s) {
        float* As = sm + s * NN_STAGE_FLOATS;
        float* Bs = As + 128 * ASTRIDE;
        const uint32_t as_u = smb + (uint32_t)(s * NN_STAGE_FLOATS) * 4;
        const uint32_t bs_u = as_u + 128 * ASTRIDE * 4;
        (void)As; (void)Bs;
        #pragma unroll
        for (int k = 0; k < 4; k++) {
            int t = tid + k * 256;
            int row = t >> 3, seg = t & 7;        // A: 128 rows x 8 segs
            CP_ASYNC16(as_u + (uint32_t)(row * ASTRIDE + seg * 4) * 4,
                       Ab + (size_t)row * lda + k0 + seg * 4);
        }
        #pragma unroll
        for (int k = 0; k < 4; k++) {
            int t = tid + k * 256;
            int row = t >> 5, seg = t & 31;       // B: 32 rows x 32 segs
            CP_ASYNC16(bs_u + (uint32_t)(row * BSTRIDE + seg * 4) * 4,
                       Bb + (size_t)(k0 + row) * ldb + seg * 4);
        }
        CP_COMMIT();
    };

    issue(0, 0);

    const int nchunks = Kdim >> 5;
    for (int c = 0; c < nchunks; c++) {
        const int s = c & 1;
        if (c + 1 < nchunks) { issue((c + 1) << 5, s ^ 1); CP_WAIT(1); }
        else                 { CP_WAIT(0); }
        __syncthreads();

        const float* As = sm + s * NN_STAGE_FLOATS;
        const float* Bs = As + 128 * ASTRIDE;

        #pragma unroll
        for (int kk = 0; kk < 4; kk++) {
            wmma::fragment<wmma::matrix_a, 16, 16, 8, wmma::precision::tf32, wmma::row_major> af[2];
            wmma::fragment<wmma::matrix_b, 16, 16, 8, wmma::precision::tf32, wmma::row_major> bf[4];
            #pragma unroll
            for (int f = 0; f < 2; f++)
                wmma::load_matrix_sync(af[f], As + (wm * 32 + f * 16) * ASTRIDE + kk * 8, ASTRIDE);
            #pragma unroll
            for (int g = 0; g < 4; g++)
                wmma::load_matrix_sync(bf[g], Bs + kk * 8 * BSTRIDE + wn * 64 + g * 16, BSTRIDE);
            #pragma unroll
            for (int f = 0; f < 2; f++)
                #pragma unroll
                for (int g = 0; g < 4; g++)
                    wmma::mma_sync(acc[f][g], af[f], bf[g], acc[f][g]);
        }
        __syncthreads();
    }

    #pragma unroll
    for (int f = 0; f < 2; f++)
        #pragma unroll
        for (int g = 0; g < 4; g++)
            wmma::store_matrix_sync(
                Cb + (size_t)(m0 + wm * 32 + f * 16) * ldc + n0 + wn * 64 + g * 16,
                acc[f][g], ldc, wmma::mem_row_major);
}

// ===========================================================================
// WMMA tf32 NT GEMM with epilogue:
//   out[b][c][i] = gamma * sum_j V[b][c][j] * P[b][i][j] + x[b][c][i]
// ===========================================================================
#define OUT_STAGE_FLOATS (2 * 128 * ASTRIDE)              // 10240
#define EPSTRIDE 132
#define SMEM_OUT_BYTES (2 * OUT_STAGE_FLOATS * 4)         // 81920 (>=128*EPSTRIDE*4)

__global__ void __launch_bounds__(256, 2)
wmma_out_kernel(const float* __restrict__ V, const float* __restrict__ P,
                const float* __restrict__ x, const float* __restrict__ gamma,
                float* __restrict__ out) {
    extern __shared__ float sm[];

    const int b  = blockIdx.z;
    const int c0 = blockIdx.y * 128;
    const int i0 = blockIdx.x * 128;
    const float* Vb = V + ((size_t)b * CC + c0) * NN;
    const float* Pb = P + ((size_t)b * NN + i0) * NN;

    const int tid = threadIdx.x;
    const int wid = tid >> 5;
    const int wm = wid >> 1;
    const int wn = wid & 1;

    wmma::fragment<wmma::accumulator, 16, 16, 8, float> acc[2][4];
    #pragma unroll
    for (int f = 0; f < 2; f++)
        #pragma unroll
        for (int g = 0; g < 4; g++)
            wmma::fill_fragment(acc[f][g], 0.0f);

    const uint32_t smb = smem_u32(sm);

    auto issue = [&](int j0, int s) {
        const uint32_t as_u = smb + (uint32_t)(s * OUT_STAGE_FLOATS) * 4;
        const uint32_t bs_u = as_u + 128 * ASTRIDE * 4;
        #pragma unroll
        for (int k = 0; k < 4; k++) {
            int t = tid + k * 256;
            int row = t >> 3, seg = t & 7;
            CP_ASYNC16(as_u + (uint32_t)(row * ASTRIDE + seg * 4) * 4,
                       Vb + (size_t)row * NN + j0 + seg * 4);
        }
        #pragma unroll
        for (int k = 0; k < 4; k++) {
            int t = tid + k * 256;
            int row = t >> 3, seg = t & 7;
            CP_ASYNC16(bs_u + (uint32_t)(row * ASTRIDE + seg * 4) * 4,
                       Pb + (size_t)row * NN + j0 + seg * 4);
        }
        CP_COMMIT();
    };

    issue(0, 0);

    const int nchunks = NN >> 5;
    for (int c = 0; c < nchunks; c++) {
        const int s = c & 1;
        if (c + 1 < nchunks) { issue((c + 1) << 5, s ^ 1); CP_WAIT(1); }
        else                 { CP_WAIT(0); }
        __syncthreads();

        const float* As = sm + s * OUT_STAGE_FLOATS;
        const float* Bs = As + 128 * ASTRIDE;

        #pragma unroll
        for (int kk = 0; kk < 4; kk++) {
            wmma::fragment<wmma::matrix_a, 16, 16, 8, wmma::precision::tf32, wmma::row_major> af[2];
            wmma::fragment<wmma::matrix_b, 16, 16, 8, wmma::precision::tf32, wmma::col_major> bf[4];
            #pragma unroll
            for (int f = 0; f < 2; f++)
                wmma::load_matrix_sync(af[f], As + (wm * 32 + f * 16) * ASTRIDE + kk * 8, ASTRIDE);
            #pragma unroll
            for (int g = 0; g < 4; g++)
                wmma::load_matrix_sync(bf[g], Bs + (wn * 64 + g * 16) * ASTRIDE + kk * 8, ASTRIDE);
            #pragma unroll
            for (int f = 0; f < 2; f++)
                #pragma unroll
                for (int g = 0; g < 4; g++)
                    wmma::mma_sync(acc[f][g], af[f], bf[g], acc[f][g]);
        }
        __syncthreads();
    }

    // Stage accumulators to smem (alias), fused epilogue out = g*acc + x
    float* Ep = sm;
    #pragma unroll
    for (int f = 0; f < 2; f++)
        #pragma unroll
        for (int g = 0; g < 4; g++)
            wmma::store_matrix_sync(Ep + (wm * 32 + f * 16) * EPSTRIDE + wn * 64 + g * 16,
                                    acc[f][g], EPSTRIDE, wmma::mem_row_major);
    __syncthreads();

    const float gm = gamma[0];
    #pragma unroll
    for (int t = tid; t < 128 * 32; t += 256) {
        int r = t >> 5, s2 = t & 31;
        float4 a = *(const float4*)(Ep + r * EPSTRIDE + s2 * 4);
        size_t gi = ((size_t)b * CC + c0 + r) * NN + i0 + s2 * 4;
        float4 xv = *(const float4*)(x + gi);
        float4 o;
        o.x = gm * a.x + xv.x;
        o.y = gm * a.y + xv.y;
        o.z = gm * a.z + xv.z;
        o.w = gm * a.w + xv.w;
        *(float4*)(out + gi) = o;
    }
}

// ---------------------------------------------------------------------------
// Projection GEMM (FFMA, Q and K only — small):
// ---------------------------------------------------------------------------
template <int M, bool TRANS>
__global__ void proj_kernel(const float* __restrict__ W,
                            const float* __restrict__ X,
                            float* __restrict__ Y) {
    __shared__ float As[64 * 17];
    __shared__ float Bs[16 * 64];

    const int b  = blockIdx.z;
    const float* Xb = X + (size_t)b * CC * NN;
    const int n0 = blockIdx.x * 64;
    const int m0 = blockIdx.y * 64;
    const int tid = threadIdx.x;
    const int tx = tid & 15;
    const int ty = tid >> 4;

    float acc[4][4] = {};

    for (int k0 = 0; k0 < CC; k0 += 16) {
        {
            int lin = tid * 4;
            int m = lin >> 4, k = lin & 15;
            float4 v = *(const float4*)(W + (size_t)(m0 + m) * CC + k0 + k);
            As[m * 17 + k + 0] = v.x; As[m * 17 + k + 1] = v.y;
            As[m * 17 + k + 2] = v.z; As[m * 17 + k + 3] = v.w;
        }
        {
            int lin = tid * 4;
            int k = lin >> 6, n = lin & 63;
            *(float4*)(Bs + k * 64 + n) =
                *(const float4*)(Xb + (size_t)(k0 + k) * NN + n0 + n);
        }
        __syncthreads();
        #pragma unroll
        for (int kk = 0; kk < 16; kk++) {
            float a[4], bv[4];
            #pragma unroll
            for (int i = 0; i < 4; i++) a[i] = As[(ty * 4 + i) * 17 + kk];
            #pragma unroll
            for (int j = 0; j < 4; j++) bv[j] = Bs[kk * 64 + tx * 4 + j];
            #pragma unroll
            for (int i = 0; i < 4; i++)
                #pragma unroll
                for (int j = 0; j < 4; j++)
                    acc[i][j] += a[i] * bv[j];
        }
        __syncthreads();
    }

    if (TRANS) {
        float* Yb = Y + (size_t)b * NN * M;
        #pragma unroll
        for (int i = 0; i < 4; i++)
            #pragma unroll
            for (int j = 0; j < 4; j++)
                Yb[(size_t)(n0 + tx * 4 + j) * M + (m0 + ty * 4 + i)] = acc[i][j];
    } else {
        float* Yb = Y + (size_t)b * M * NN;
        #pragma unroll
        for (int i = 0; i < 4; i++)
            #pragma unroll
            for (int j = 0; j < 4; j++)
                Yb[(size_t)(m0 + ty * 4 + i) * NN + (n0 + tx * 4 + j)] = acc[i][j];
    }
}

// ---------------------------------------------------------------------------
// Row softmax over keys. One block per (b, row), 256 threads.
// ---------------------------------------------------------------------------
__global__ void softmax_kernel(float* __restrict__ P) {
    const size_t roff = ((size_t)blockIdx.y * NN + blockIdx.x) * (size_t)NN;
    float4* p4 = (float4*)(P + roff);
    const int tid = threadIdx.x;

    __shared__ float sh_max[8];
    __shared__ float sh_sum[8];
    __shared__ float sh_bcast;

    float4 v[4];
    float m = -1e30f;
    #pragma unroll
    for (int q = 0; q < 4; q++) {
        v[q] = p4[tid + q * 256];
        m = fmaxf(m, fmaxf(fmaxf(v[q].x, v[q].y), fmaxf(v[q].z, v[q].w)));
    }
    #pragma unroll
    for (int o = 16; o > 0; o >>= 1) m = fmaxf(m, __shfl_xor_sync(0xffffffffu, m, o));
    if ((tid & 31) == 0) sh_max[tid >> 5] = m;
    __syncthreads();
    if (tid == 0) {
        float t = sh_max[0];
        #pragma unroll
        for (int w = 1; w < 8; w++) t = fmaxf(t, sh_max[w]);
        sh_bcast = t;
    }
    __syncthreads();
    m = sh_bcast;

    float s = 0.f;
    #pragma unroll
    for (int q = 0; q < 4; q++) {
        v[q].x = expf(v[q].x - m); v[q].y = expf(v[q].y - m);
        v[q].z = expf(v[q].z - m); v[q].w = expf(v[q].w - m);
        s += v[q].x + v[q].y + v[q].z + v[q].w;
    }
    #pragma unroll
    for (int o = 16; o > 0; o >>= 1) s += __shfl_xor_sync(0xffffffffu, s, o);
    if ((tid & 31) == 0) sh_sum[tid >> 5] = s;
    __syncthreads();
    if (tid == 0) {
        float t = 0.f;
        #pragma unroll
        for (int w = 0; w < 8; w++) t += sh_sum[w];
        sh_bcast = 1.0f / t;
    }
    __syncthreads();
    const float inv = sh_bcast;

    #pragma unroll
    for (int q = 0; q < 4; q++) {
        v[q].x *= inv; v[q].y *= inv; v[q].z *= inv; v[q].w *= inv;
        p4[tid + q * 256] = v[q];
    }
}

// ---------------------------------------------------------------------------
extern "C" void kernel_launch(void* const* d_in, const int* in_sizes, int n_in,
                              void* d_out, int out_size) {
    const float* x     = (const float*)d_in[0];
    const float* Wq    = (const float*)d_in[1];
    const float* Wk    = (const float*)d_in[2];
    const float* Wv    = (const float*)d_in[3];
    const float* gamma = (const float*)d_in[4];
    float* out = (float*)d_out;

    float *Q, *K, *V, *P;
    cudaGetSymbolAddress((void**)&Q, g_Q);
    cudaGetSymbolAddress((void**)&K, g_K);
    cudaGetSymbolAddress((void**)&V, g_V);
    cudaGetSymbolAddress((void**)&P, g_P);

    cudaFuncSetAttribute(wmma_nn_kernel,
                         cudaFuncAttributeMaxDynamicSharedMemorySize, SMEM_NN_BYTES);
    cudaFuncSetAttribute(wmma_out_kernel,
                         cudaFuncAttributeMaxDynamicSharedMemorySize, SMEM_OUT_BYTES);

    dim3 blk(256);

    // Q, K projections (FFMA; small)
    proj_kernel<CQ, true ><<<dim3(NN / 64, CQ / 64, BB), blk>>>(Wq, x, Q);
    proj_kernel<CQ, false><<<dim3(NN / 64, CQ / 64, BB), blk>>>(Wk, x, K);

    // V projection (WMMA tf32)
    wmma_nn_kernel<<<dim3(NN / 128, CC / 128, BB), blk, SMEM_NN_BYTES>>>(
        Wv, x, V, CC, CC, NN, NN,
        0, (size_t)CC * NN, (size_t)CC * NN);

    // Energy (WMMA tf32)
    wmma_nn_kernel<<<dim3(NN / 128, NN / 128, BB), blk, SMEM_NN_BYTES>>>(
        Q, K, P, CQ, CQ, NN, NN,
        (size_t)NN * CQ, (size_t)CQ * NN, (size_t)NN * NN);

    // Softmax over keys
    softmax_kernel<<<dim3(NN, BB), blk>>>(P);

    // Output GEMM + fused epilogue (WMMA tf32, B transposed)
    wmma_out_kernel<<<dim3(NN / 128, CC / 128, BB), blk, SMEM_OUT_BYTES>>>(
        V, P, x, gamma, out);
}